// round 13
// baseline (speedup 1.0000x reference)
#include <cuda_runtime.h>
#include <cuda_bf16.h>
#include <cstdint>

// MaxUnpooling2DMod: out[b, y(idx), x(idx), c] += in[b,h,w,c]
//   in  [8,128,128,64] -> 2^23 floats, out [8,256,256,64] -> 2^25 floats
// decode: out_off = (b << 22) + (idx & ~63) + (lin & 63)
//
// FOUR parallel PDL skip-chains (stream k handles batches k and k+4):
//   z_k -> s_k -> z_{k+4} -> s_{k+4}
// z: zero slab, no wait, trigger after stores. s: trigger at entry (releases
// next z in this stream), loads, wait (-> immediate predecessor z completion),
// REDG. Up to 4 scatter grids' atomics in flight: cross-grid concurrency is
// the only lever that has moved aggregate atomic throughput (R8/R12 data).

static constexpr int BLOCK = 256;

// ---- zero kernel: 512 blocks x 8 float4 (low SM-slot footprint) ----
static constexpr int ZGRID      = 512;
static constexpr int ZTHREADS   = ZGRID * BLOCK;          // 131072
static constexpr int SLAB_F4    = (1 << 22) / 4;          // 1,048,576 float4
static constexpr int ZERO_PER_T = SLAB_F4 / ZTHREADS;     // 8

__global__ void __launch_bounds__(BLOCK)
zero_slab_kernel(float* __restrict__ out, int slab)
{
    const int t = blockIdx.x * BLOCK + threadIdx.x;
    float4* o4 = reinterpret_cast<float4*>(out) + (size_t)slab * SLAB_F4;
    const float4 z = make_float4(0.f, 0.f, 0.f, 0.f);
    #pragma unroll
    for (int j = 0; j < ZERO_PER_T; j++)
        o4[t + j * ZTHREADS] = z;
    asm volatile("griddepcontrol.launch_dependents;" ::: "memory");
}

// ---- scatter kernel: 2048 blocks x 2 elems (best measured shape) ----
static constexpr int SGRID = 2048;

__global__ void __launch_bounds__(BLOCK)
scatter_kernel(const float* __restrict__ in,
               const int*   __restrict__ idx,
               float*       __restrict__ out,
               int b)
{
    // Release this stream's next kernel (zero of a disjoint slab) immediately.
    asm volatile("griddepcontrol.launch_dependents;" ::: "memory");

    const int t  = blockIdx.x * BLOCK + threadIdx.x;      // 524288 threads
    const int e0 = (b << 20) + (t << 1);                  // 2 elems/thread

    const float2 v  = __ldcs(reinterpret_cast<const float2*>(in)  + (e0 >> 1));
    const int2   id = __ldcs(reinterpret_cast<const int2*>(idx)   + (e0 >> 1));

    // Wait for immediate predecessor (z_b) completion: slab b zeroed+visible.
    asm volatile("griddepcontrol.wait;" ::: "memory");

    const int base = b << 22;
    const int c0   = e0 & 63;
    atomicAdd(out + base + (id.x & ~63) + (c0 + 0), v.x);
    atomicAdd(out + base + (id.y & ~63) + (c0 + 1), v.y);
}

extern "C" void kernel_launch(void* const* d_in, const int* in_sizes, int n_in,
                              void* d_out, int out_size)
{
    const float* in  = (const float*)d_in[0];
    const int*   idx = (const int*)d_in[1];
    float*       out = (float*)d_out;

    // 3 extra streams + fork/join events (host objects only, created once).
    static cudaStream_t s[4] = {nullptr, nullptr, nullptr, nullptr};
    static cudaEvent_t  evFork = nullptr, evJoin[4] = {};
    if (s[1] == nullptr) {
        s[0] = 0;
        for (int k = 1; k < 4; k++)
            cudaStreamCreateWithFlags(&s[k], cudaStreamNonBlocking);
        cudaEventCreateWithFlags(&evFork, cudaEventDisableTiming);
        for (int k = 1; k < 4; k++)
            cudaEventCreateWithFlags(&evJoin[k], cudaEventDisableTiming);
    }

    cudaLaunchAttribute attrs[1];
    attrs[0].id = cudaLaunchAttributeProgrammaticStreamSerialization;
    attrs[0].val.programmaticStreamSerializationAllowed = 1;

    // Fork side streams off stream 0.
    cudaEventRecord(evFork, 0);
    for (int k = 1; k < 4; k++)
        cudaStreamWaitEvent(s[k], evFork, 0);

    cudaLaunchConfig_t cfg = {};
    cfg.blockDim = dim3(BLOCK, 1, 1);

    // Stream k runs its own PDL skip-chain over batches {k, k+4}.
    for (int k = 0; k < 4; k++) {
        cfg.stream = s[k];
        for (int j = 0; j < 2; j++) {
            const int b = k + 4 * j;

            cfg.gridDim = dim3(ZGRID, 1, 1);
            cfg.attrs    = (j == 0) ? nullptr : attrs;    // first z per stream
            cfg.numAttrs = (j == 0) ? 0 : 1;
            cudaLaunchKernelEx(&cfg, zero_slab_kernel, out, b);

            cfg.gridDim = dim3(SGRID, 1, 1);
            cfg.attrs = attrs;  cfg.numAttrs = 1;
            cudaLaunchKernelEx(&cfg, scatter_kernel, in, idx, out, b);
        }
    }

    // Join all side streams back into stream 0.
    for (int k = 1; k < 4; k++) {
        cudaEventRecord(evJoin[k], s[k]);
        cudaStreamWaitEvent(0, evJoin[k], 0);
    }
}

// round 14
// speedup vs baseline: 1.1152x; 1.1152x over previous
#include <cuda_runtime.h>
#include <cuda_bf16.h>
#include <cstdint>

// MaxUnpooling2DMod: out[b, y(idx), x(idx), c] += in[b,h,w,c]
//   in  [8,128,128,64] -> 2^23 floats, out [8,256,256,64] -> 2^25 floats
// decode: out_off = (b << 22) + (idx & ~63) + (lin & 63)
//
// THREE parallel PDL skip-chains:
//   stream0: b0,b3,b6   stream1: b1,b4,b7   stream2: b2,b5
// Each chain: z_b (zero slab, trigger after stores) -> s_b (trigger at entry,
// load, wait->z_b completion, REDG) -> next z.
// Live L2 set <= 6 slabs = 100MB < 126MB (4 chains = 134MB thrashed, R13).
// 3 concurrent scatter grids: cross-grid concurrency is the only lever that
// raises aggregate atomic throughput (R8/R12/R13 scaling data).

static constexpr int BLOCK = 256;

// ---- zero kernel: 512 blocks x 8 float4 ----
static constexpr int ZGRID      = 512;
static constexpr int ZTHREADS   = ZGRID * BLOCK;          // 131072
static constexpr int SLAB_F4    = (1 << 22) / 4;          // 1,048,576 float4
static constexpr int ZERO_PER_T = SLAB_F4 / ZTHREADS;     // 8

__global__ void __launch_bounds__(BLOCK)
zero_slab_kernel(float* __restrict__ out, int slab)
{
    const int t = blockIdx.x * BLOCK + threadIdx.x;
    float4* o4 = reinterpret_cast<float4*>(out) + (size_t)slab * SLAB_F4;
    const float4 z = make_float4(0.f, 0.f, 0.f, 0.f);
    #pragma unroll
    for (int j = 0; j < ZERO_PER_T; j++)
        o4[t + j * ZTHREADS] = z;
    asm volatile("griddepcontrol.launch_dependents;" ::: "memory");
}

// ---- scatter kernel: 2048 blocks x 2 elems (best measured shape) ----
static constexpr int SGRID = 2048;

__global__ void __launch_bounds__(BLOCK)
scatter_kernel(const float* __restrict__ in,
               const int*   __restrict__ idx,
               float*       __restrict__ out,
               int b)
{
    // Release this stream's next kernel (zero of a disjoint slab) immediately.
    asm volatile("griddepcontrol.launch_dependents;" ::: "memory");

    const int t  = blockIdx.x * BLOCK + threadIdx.x;      // 524288 threads
    const int e0 = (b << 20) + (t << 1);                  // 2 elems/thread

    const float2 v  = __ldcs(reinterpret_cast<const float2*>(in)  + (e0 >> 1));
    const int2   id = __ldcs(reinterpret_cast<const int2*>(idx)   + (e0 >> 1));

    // Wait for immediate predecessor (z_b) completion: slab b zeroed+visible.
    asm volatile("griddepcontrol.wait;" ::: "memory");

    const int base = b << 22;
    const int c0   = e0 & 63;
    atomicAdd(out + base + (id.x & ~63) + (c0 + 0), v.x);
    atomicAdd(out + base + (id.y & ~63) + (c0 + 1), v.y);
}

extern "C" void kernel_launch(void* const* d_in, const int* in_sizes, int n_in,
                              void* d_out, int out_size)
{
    const float* in  = (const float*)d_in[0];
    const int*   idx = (const int*)d_in[1];
    float*       out = (float*)d_out;

    // 2 extra streams + fork/join events (host objects only, created once).
    static cudaStream_t s[3] = {nullptr, nullptr, nullptr};
    static cudaEvent_t  evFork = nullptr, evJoin[3] = {};
    if (s[1] == nullptr) {
        s[0] = 0;
        for (int k = 1; k < 3; k++)
            cudaStreamCreateWithFlags(&s[k], cudaStreamNonBlocking);
        cudaEventCreateWithFlags(&evFork, cudaEventDisableTiming);
        for (int k = 1; k < 3; k++)
            cudaEventCreateWithFlags(&evJoin[k], cudaEventDisableTiming);
    }

    cudaLaunchAttribute attrs[1];
    attrs[0].id = cudaLaunchAttributeProgrammaticStreamSerialization;
    attrs[0].val.programmaticStreamSerializationAllowed = 1;

    // Fork side streams off stream 0.
    cudaEventRecord(evFork, 0);
    for (int k = 1; k < 3; k++)
        cudaStreamWaitEvent(s[k], evFork, 0);

    cudaLaunchConfig_t cfg = {};
    cfg.blockDim = dim3(BLOCK, 1, 1);

    // Stream k handles batches k, k+3, k+6 (stream 2: just b2, b5).
    for (int k = 0; k < 3; k++) {
        cfg.stream = s[k];
        for (int b = k, j = 0; b < 8; b += 3, j++) {
            cfg.gridDim = dim3(ZGRID, 1, 1);
            cfg.attrs    = (j == 0) ? nullptr : attrs;    // first z per stream
            cfg.numAttrs = (j == 0) ? 0 : 1;
            cudaLaunchKernelEx(&cfg, zero_slab_kernel, out, b);

            cfg.gridDim = dim3(SGRID, 1, 1);
            cfg.attrs = attrs;  cfg.numAttrs = 1;
            cudaLaunchKernelEx(&cfg, scatter_kernel, in, idx, out, b);
        }
    }

    // Join side streams back into stream 0.
    for (int k = 1; k < 3; k++) {
        cudaEventRecord(evJoin[k], s[k]);
        cudaStreamWaitEvent(0, evJoin[k], 0);
    }
}